// round 13
// baseline (speedup 1.0000x reference)
#include <cuda_runtime.h>
#include <math.h>

#define B 32
#define NTOK 4096
#define C 768
#define H 12
#define CH 16           // outer chunks per batch (256 tokens each)
#define SUBS 8          // sub-chunks per CTA
#define TPC 32          // tokens per sub-chunk tile
#define XSTR 772        // xs row stride in floats (768 + 4: conflict-free pad)

typedef unsigned long long u64;

// ---------------- scratch ----------------
__device__ __align__(16) float g_qp[4 * B * C];     // K-split partials of q (pre-scaled)
__device__ __align__(16) float g_t[B * C * H];
__device__ __align__(16) float g_cl[B * CH * H];
__device__ __align__(16) float g_yp[CH * B * H * C];
__device__ __align__(16) float g_cls[B * C];

// ---------------- f32x2 helpers ----------------
#define FMA2(d, a, b) asm("fma.rn.f32x2 %0, %1, %2, %0;" : "+l"(d) : "l"(a), "l"(b))
#define ADD2(d, a)    asm("add.rn.f32x2 %0, %0, %1;"     : "+l"(d) : "l"(a))

__device__ __forceinline__ u64 dup2(float v) {
    u64 r;
    asm("mov.b64 %0, {%1, %1};" : "=l"(r) : "r"(__float_as_uint(v)));
    return r;
}
__device__ __forceinline__ float2 unpk(u64 p) {
    float2 r;
    r.x = __uint_as_float((unsigned int)p);
    r.y = __uint_as_float((unsigned int)(p >> 32));
    return r;
}

// smem map for k_fused (unchanged from R12)
#define OFF_T2S   98816
#define OFF_W2S   111104
#define OFF_REDL  114176
#define FUSED_SMEM 114304

// ---------------- K0a: q partials — weight-stationary, grid (12, 4) ----------------
// q[b, j] = 0.125 * sum_c x[b,0,c] Wq[c,j];  this CTA: cols jj*64..+64, c in [ks*192, +192)
__global__ void k_q_kern(const float* __restrict__ x, const float* __restrict__ Wq) {
    int jj = blockIdx.x, ks = blockIdx.y, tid = threadIdx.x;
    __shared__ float xsT[192 * 36];                 // [k_local][b], stride 36
    #pragma unroll
    for (int j = 0; j < 6; j++) {
        int idx = (tid + j * 256) * 4;              // 6144 floats total
        int b = idx / 192, k = idx % 192;
        float4 v = *(const float4*)(x + (size_t)b * NTOK * C + ks * 192 + k);
        xsT[(k + 0) * 36 + b] = v.x;
        xsT[(k + 1) * 36 + b] = v.y;
        xsT[(k + 2) * 36 + b] = v.z;
        xsT[(k + 3) * 36 + b] = v.w;
    }
    __syncthreads();
    int col = jj * 64 + (tid & 63), bq = tid >> 6;  // bq<4, 8 b's each
    float acc[8];
    #pragma unroll
    for (int i = 0; i < 8; i++) acc[i] = 0.f;
    const float* wcol = Wq + (size_t)(ks * 192) * C + col;
    #pragma unroll 4
    for (int kk = 0; kk < 192; kk++) {
        float w = wcol[(size_t)kk * C];
        float4 xa = *(const float4*)&xsT[kk * 36 + bq * 8];
        float4 xb = *(const float4*)&xsT[kk * 36 + bq * 8 + 4];
        acc[0] = fmaf(xa.x, w, acc[0]); acc[1] = fmaf(xa.y, w, acc[1]);
        acc[2] = fmaf(xa.z, w, acc[2]); acc[3] = fmaf(xa.w, w, acc[3]);
        acc[4] = fmaf(xb.x, w, acc[4]); acc[5] = fmaf(xb.y, w, acc[5]);
        acc[6] = fmaf(xb.z, w, acc[6]); acc[7] = fmaf(xb.w, w, acc[7]);
    }
    #pragma unroll
    for (int i = 0; i < 8; i++)
        g_qp[(size_t)ks * B * C + (size_t)(bq * 8 + i) * C + col] = acc[i] * 0.125f;
}

// ---------------- K0b: t — weight-stationary, grid (48), arg bg in {0,1} ----------------
// t[b, c, h] = sum_d Wk[c, h*64+d] q[b, h*64+d];  CTA: c rows cb*16..+16, b in [bg*16, +16)
__global__ void k_t_kern(const float* __restrict__ Wkv, int bg) {
    __shared__ float wk[16 * 772];
    __shared__ float qs[16 * 772];
    int cb = blockIdx.x, tid = threadIdx.x;
    int c0 = cb * 16;
    #pragma unroll
    for (int j = 0; j < 12; j++) {
        int idx = (tid + j * 256) * 4;              // 12288 floats
        int row = idx / 768, k = idx % 768;
        *(float4*)&wk[row * 772 + k] =
            *(const float4*)(Wkv + (size_t)(c0 + row) * (2 * C) + k);
        int b = bg * 16 + row;
        float4 q0 = *(const float4*)(g_qp + (size_t)0 * B * C + (size_t)b * C + k);
        float4 q1 = *(const float4*)(g_qp + (size_t)1 * B * C + (size_t)b * C + k);
        float4 q2 = *(const float4*)(g_qp + (size_t)2 * B * C + (size_t)b * C + k);
        float4 q3 = *(const float4*)(g_qp + (size_t)3 * B * C + (size_t)b * C + k);
        float4 s;
        s.x = (q0.x + q1.x) + (q2.x + q3.x);
        s.y = (q0.y + q1.y) + (q2.y + q3.y);
        s.z = (q0.z + q1.z) + (q2.z + q3.z);
        s.w = (q0.w + q1.w) + (q2.w + q3.w);
        *(float4*)&qs[row * 772 + k] = s;
    }
    __syncthreads();
    int cl = tid & 15, bb = tid >> 4;
    float th[12];
    #pragma unroll
    for (int h = 0; h < 12; h++) {
        float a0 = 0.f, a1 = 0.f, a2 = 0.f, a3 = 0.f;
        #pragma unroll
        for (int j = 0; j < 16; j++) {
            float4 w = *(const float4*)&wk[cl * 772 + h * 64 + j * 4];
            float4 qv = *(const float4*)&qs[bb * 772 + h * 64 + j * 4];
            a0 = fmaf(w.x, qv.x, a0); a1 = fmaf(w.y, qv.y, a1);
            a2 = fmaf(w.z, qv.z, a2); a3 = fmaf(w.w, qv.w, a3);
        }
        th[h] = (a0 + a1) + (a2 + a3);
    }
    int b = bg * 16 + bb;
    float* tp = g_t + (size_t)b * C * H + (size_t)(c0 + cl) * H;
    *(float4*)&tp[0] = make_float4(th[0], th[1], th[2], th[3]);
    *(float4*)&tp[4] = make_float4(th[4], th[5], th[6], th[7]);
    *(float4*)&tp[8] = make_float4(th[8], th[9], th[10], th[11]);
}

// ---------------- K1 fused (UNCHANGED from R12): x resident in smem ----------------
__global__ void __launch_bounds__(256, 2) k_fused(const float* __restrict__ x) {
    extern __shared__ __align__(16) char dyn[];
    float* xs = (float*)dyn;
    u64* t2s = (u64*)(dyn + OFF_T2S);
    u64* w2s = (u64*)(dyn + OFF_W2S);
    float* redl = (float*)(dyn + OFF_REDL);

    int b = blockIdx.y, ch = blockIdx.x, tid = threadIdx.x;
    int wid = tid >> 5, lane = tid & 31;
    int pp = tid >> 4, np = tid & 15;
    int g = tid >> 7, ct = tid & 127;
    const float* tb = g_t + (size_t)b * C * H;
    const u64* tsrc = (const u64*)tb;

    unsigned sxs = (unsigned)__cvta_generic_to_shared(xs);
    unsigned st2 = (unsigned)__cvta_generic_to_shared(t2s);

    u64 ya[6][3];
    #pragma unroll
    for (int hh = 0; hh < 6; hh++) {
        #pragma unroll
        for (int pc = 0; pc < 3; pc++) ya[hh][pc] = 0ull;
    }
    float lacc[4] = {0.f, 0.f, 0.f, 0.f};

    #pragma unroll 1
    for (int s = 0; s < SUBS; s++) {
        const float* xrow = x + ((size_t)b * NTOK + (size_t)(ch * 256 + s * TPC)) * C;

        #pragma unroll
        for (int j = 0; j < 24; j++) {
            int f = tid * 4 + j * 1024;
            int n = f / 768;
            asm volatile("cp.async.cg.shared.global [%0], [%1], 16;\n" ::
                         "r"(sxs + (unsigned)(f * 4 + n * 16)), "l"(xrow + f) : "memory");
        }
        asm volatile("cp.async.commit_group;\n" ::: "memory");

        {
            unsigned d0 = st2 + tid * 8;
            asm volatile("cp.async.ca.shared.global [%0], [%1], 8;\n" ::
                         "r"(d0), "l"(tsrc + tid) : "memory");
            asm volatile("cp.async.ca.shared.global [%0], [%1], 8;\n" ::
                         "r"(d0 + 2048), "l"(tsrc + 256 + tid) : "memory");
            asm volatile("cp.async.ca.shared.global [%0], [%1], 8;\n" ::
                         "r"(d0 + 4096), "l"(tsrc + 512 + tid) : "memory");
            asm volatile("cp.async.commit_group;\n" ::: "memory");
        }

        u64 acc0[6], acc1[6];
        #pragma unroll
        for (int i = 0; i < 6; i++) { acc0[i] = 0ull; acc1[i] = 0ull; }

        #pragma unroll
        for (int r = 0; r < 6; r++) {
            asm volatile("cp.async.wait_group 0;\n" ::: "memory");
            __syncthreads();
            if (r < 5) {
                unsigned d = st2 + (unsigned)(((r + 1) & 1) * 6144) + tid * 8;
                const u64* srcr = tsrc + (r + 1) * 768;
                asm volatile("cp.async.ca.shared.global [%0], [%1], 8;\n" ::
                             "r"(d), "l"(srcr + tid) : "memory");
                asm volatile("cp.async.ca.shared.global [%0], [%1], 8;\n" ::
                             "r"(d + 2048), "l"(srcr + 256 + tid) : "memory");
                asm volatile("cp.async.ca.shared.global [%0], [%1], 8;\n" ::
                             "r"(d + 4096), "l"(srcr + 512 + tid) : "memory");
                asm volatile("cp.async.commit_group;\n" ::: "memory");
            }

            const u64* tbuf = t2s + (r & 1) * 768;
            int cb = r * 128 + pp * 8;
            float xa0[8], xa1[8];
            *(float4*)&xa0[0] = *(const float4*)&xs[np * XSTR + cb];
            *(float4*)&xa0[4] = *(const float4*)&xs[np * XSTR + cb + 4];
            *(float4*)&xa1[0] = *(const float4*)&xs[(np + 16) * XSTR + cb];
            *(float4*)&xa1[4] = *(const float4*)&xs[(np + 16) * XSTR + cb + 4];
            #pragma unroll
            for (int e = 0; e < 8; e++) {
                const u64* tp = &tbuf[(pp * 8 + e) * 6];
                ulonglong2 ta = *(const ulonglong2*)&tp[0];
                ulonglong2 tb2 = *(const ulonglong2*)&tp[2];
                ulonglong2 tc = *(const ulonglong2*)&tp[4];
                u64 d0 = dup2(xa0[e]);
                u64 d1 = dup2(xa1[e]);
                FMA2(acc0[0], d0, ta.x);  FMA2(acc0[1], d0, ta.y);
                FMA2(acc0[2], d0, tb2.x); FMA2(acc0[3], d0, tb2.y);
                FMA2(acc0[4], d0, tc.x);  FMA2(acc0[5], d0, tc.y);
                FMA2(acc1[0], d1, ta.x);  FMA2(acc1[1], d1, ta.y);
                FMA2(acc1[2], d1, tb2.x); FMA2(acc1[3], d1, tb2.y);
                FMA2(acc1[4], d1, tc.x);  FMA2(acc1[5], d1, tc.y);
            }
        }
        __syncthreads();

        ulonglong2* redq = (ulonglong2*)t2s;
        redq[tid]       = make_ulonglong2(acc0[0], acc0[1]);
        redq[256 + tid] = make_ulonglong2(acc0[2], acc0[3]);
        redq[512 + tid] = make_ulonglong2(acc0[4], acc0[5]);
        __syncthreads();
        u64 sx = 0ull, sy = 0ull;
        if (wid < 3 && lane < 16) {
            #pragma unroll
            for (int p2 = 0; p2 < 16; p2++) {
                ulonglong2 v = redq[wid * 256 + p2 * 16 + lane];
                ADD2(sx, v.x); ADD2(sy, v.y);
            }
        }
        __syncthreads();
        redq[tid]       = make_ulonglong2(acc1[0], acc1[1]);
        redq[256 + tid] = make_ulonglong2(acc1[2], acc1[3]);
        redq[512 + tid] = make_ulonglong2(acc1[4], acc1[5]);
        __syncthreads();
        if (wid < 3 && lane < 16) {
            float2 a0 = unpk(sx), a1 = unpk(sy);
            float e0 = __expf(a0.x), e1 = __expf(a0.y);
            float e2 = __expf(a1.x), e3 = __expf(a1.y);
            int base = lane * 12 + 4 * wid;
            *(ulonglong2*)&w2s[base]     = make_ulonglong2(dup2(e0), dup2(e1));
            *(ulonglong2*)&w2s[base + 2] = make_ulonglong2(dup2(e2), dup2(e3));
            lacc[0] += e0; lacc[1] += e1; lacc[2] += e2; lacc[3] += e3;
        } else if (wid < 6 && lane < 16) {
            int j2 = wid - 3;
            u64 tx = 0ull, ty = 0ull;
            #pragma unroll
            for (int p2 = 0; p2 < 16; p2++) {
                ulonglong2 v = redq[j2 * 256 + p2 * 16 + lane];
                ADD2(tx, v.x); ADD2(ty, v.y);
            }
            float2 a0 = unpk(tx), a1 = unpk(ty);
            float e0 = __expf(a0.x), e1 = __expf(a0.y);
            float e2 = __expf(a1.x), e3 = __expf(a1.y);
            int base = (lane + 16) * 12 + 4 * j2;
            *(ulonglong2*)&w2s[base]     = make_ulonglong2(dup2(e0), dup2(e1));
            *(ulonglong2*)&w2s[base + 2] = make_ulonglong2(dup2(e2), dup2(e3));
            lacc[0] += e0; lacc[1] += e1; lacc[2] += e2; lacc[3] += e3;
        }
        __syncthreads();

        const u64* wbase = w2s + g * 6;
        #pragma unroll 8
        for (int n = 0; n < TPC; n++) {
            ulonglong2 A = *(const ulonglong2*)&xs[n * XSTR + 4 * ct];
            u64 Bv = *(const u64*)&xs[n * XSTR + 512 + 2 * ct];
            const u64* wr = wbase + n * 12;
            ulonglong2 w01 = *(const ulonglong2*)&wr[0];
            ulonglong2 w23 = *(const ulonglong2*)&wr[2];
            ulonglong2 w45 = *(const ulonglong2*)&wr[4];
            FMA2(ya[0][0], A.x, w01.x); FMA2(ya[0][1], A.y, w01.x); FMA2(ya[0][2], Bv, w01.x);
            FMA2(ya[1][0], A.x, w01.y); FMA2(ya[1][1], A.y, w01.y); FMA2(ya[1][2], Bv, w01.y);
            FMA2(ya[2][0], A.x, w23.x); FMA2(ya[2][1], A.y, w23.x); FMA2(ya[2][2], Bv, w23.x);
            FMA2(ya[3][0], A.x, w23.y); FMA2(ya[3][1], A.y, w23.y); FMA2(ya[3][2], Bv, w23.y);
            FMA2(ya[4][0], A.x, w45.x); FMA2(ya[4][1], A.y, w45.x); FMA2(ya[4][2], Bv, w45.x);
            FMA2(ya[5][0], A.x, w45.y); FMA2(ya[5][1], A.y, w45.y); FMA2(ya[5][2], Bv, w45.y);
        }
        __syncthreads();
    }

    u64* ypu = (u64*)(g_yp + (((size_t)ch * B + b) * H + g * 6) * C);
    #pragma unroll
    for (int hh = 0; hh < 6; hh++) {
        *(ulonglong2*)(ypu + (size_t)hh * 384 + 2 * ct) = make_ulonglong2(ya[hh][0], ya[hh][1]);
        ypu[(size_t)hh * 384 + 256 + ct] = ya[hh][2];
    }

    #pragma unroll
    for (int i = 0; i < 4; i++) {
        #pragma unroll
        for (int o = 16; o; o >>= 1)
            lacc[i] += __shfl_xor_sync(0xffffffffu, lacc[i], o);
    }
    if (wid >= 3 && wid < 6 && lane == 0) {
        #pragma unroll
        for (int i = 0; i < 4; i++) redl[(wid - 3) * 4 + i] = lacc[i];
    }
    __syncthreads();
    if (wid < 3 && lane == 0) {
        #pragma unroll
        for (int i = 0; i < 4; i++)
            g_cl[((size_t)b * CH + ch) * H + 4 * wid + i] = lacc[i] + redl[wid * 4 + i];
    }
}

// ---------------- K2: cls — weight-stationary, grid (12 heads, 8 b-groups of 4) ----------------
__global__ void k_cls(const float* __restrict__ Wkv) {
    int h = blockIdx.x, bg = blockIdx.y, tid = threadIdx.x;
    __shared__ float ys[4 * 768];
    __shared__ float rsc_s[4];
    if (tid < 4) {
        int b = bg * 4 + tid;
        float L = 0.f;
        #pragma unroll
        for (int ch = 0; ch < CH; ch++) L += g_cl[(size_t)b * CH * H + ch * H + h];
        rsc_s[tid] = 1.f / L;
    }
    __syncthreads();
    #pragma unroll
    for (int j = 0; j < 3; j++) {
        int idx = (tid + j * 256) * 4;              // 3072 floats
        int bl = idx / 768, c = idx % 768;
        int b = bg * 4 + bl;
        float4 s = make_float4(0.f, 0.f, 0.f, 0.f);
        #pragma unroll
        for (int ch = 0; ch < CH; ch++) {
            float4 v = *(const float4*)(g_yp + (((size_t)ch * B + b) * H + h) * C + c);
            s.x += v.x; s.y += v.y; s.z += v.z; s.w += v.w;
        }
        float r = rsc_s[bl];
        s.x *= r; s.y *= r; s.z *= r; s.w *= r;
        *(float4*)&ys[bl * 768 + c] = s;
    }
    __syncthreads();
    int dj = tid & 63, bl = tid >> 6;               // 1 output per thread
    float acc = 0.f;
    const float* wcol = Wkv + C + h * 64 + dj;      // V half
    const float* yrow = &ys[bl * 768];
    #pragma unroll 4
    for (int c = 0; c < 768; c++)
        acc = fmaf(yrow[c], wcol[(size_t)c * (2 * C)], acc);
    g_cls[(size_t)(bg * 4 + bl) * C + h * 64 + dj] = acc;
}

// ---------------- K3: out — weight-stationary, grid (12 col-blocks, 8 b-groups of 4) ----------------
__global__ void k_out(const float* __restrict__ Wp, const float* __restrict__ bp,
                      float* __restrict__ out) {
    int jj = blockIdx.x, bg = blockIdx.y, tid = threadIdx.x;
    __shared__ float cs[4 * 768];
    #pragma unroll
    for (int j = 0; j < 3; j++) {
        int idx = (tid + j * 256) * 4;
        int bl = idx / 768, c = idx % 768;
        *(float4*)&cs[bl * 768 + c] =
            *(const float4*)(g_cls + (size_t)(bg * 4 + bl) * C + c);
    }
    __syncthreads();
    int col = jj * 64 + (tid & 63), bl = tid >> 6;
    float acc = 0.f;
    const float* wcol = Wp + col;
    const float* crow = &cs[bl * 768];
    #pragma unroll 4
    for (int i = 0; i < 768; i++)
        acc = fmaf(crow[i], wcol[(size_t)i * C], acc);
    out[(size_t)(bg * 4 + bl) * C + col] = acc + bp[col];
}

// ---------------- launcher ----------------
extern "C" void kernel_launch(void* const* d_in, const int* in_sizes, int n_in,
                              void* d_out, int out_size) {
    const float* x   = (const float*)d_in[0];
    const float* Wq  = (const float*)d_in[1];
    const float* Wkv = (const float*)d_in[2];
    const float* Wp  = (const float*)d_in[3];
    const float* bp  = (const float*)d_in[4];
    float* out = (float*)d_out;

    cudaFuncSetAttribute(k_fused, cudaFuncAttributeMaxDynamicSharedMemorySize, FUSED_SMEM);

    k_q_kern<<<dim3(12, 4), 256>>>(x, Wq);             // launch #1
    k_t_kern<<<48, 256>>>(Wkv, 0);                     // launch #2
    k_t_kern<<<48, 256>>>(Wkv, 1);                     // launch #3
    k_fused <<<dim3(CH, B), 256, FUSED_SMEM>>>(x);     // launch #4 -> profiled
    k_cls   <<<dim3(12, 8), 256>>>(Wkv);               // launch #5
    k_out   <<<dim3(12, 8), 256>>>(Wp, bp, out);       // launch #6
}

// round 14
// speedup vs baseline: 1.4635x; 1.4635x over previous
#include <cuda_runtime.h>
#include <math.h>

#define B 32
#define NTOK 4096
#define C 768
#define H 12
#define CH 16           // chunks per batch (256 tokens each)
#define SUBS 8          // sub-chunks per CTA
#define TPC 32          // tokens per sub-chunk tile
#define XSTR 772        // xs row stride in floats

typedef unsigned long long u64;

// ---------------- scratch ----------------
__device__ __align__(16) float g_q[B * C];
__device__ __align__(16) float g_t[B * C * H];
__device__ __align__(16) float g_cl[B * CH * H];
__device__ __align__(16) float g_yp[CH * B * H * C];
__device__ __align__(16) float g_cls[B * C];

// ---------------- f32x2 helpers ----------------
#define FMA2(d, a, b) asm("fma.rn.f32x2 %0, %1, %2, %0;" : "+l"(d) : "l"(a), "l"(b))
#define ADD2(d, a)    asm("add.rn.f32x2 %0, %0, %1;"     : "+l"(d) : "l"(a))

__device__ __forceinline__ u64 dup2(float v) {
    u64 r;
    asm("mov.b64 %0, {%1, %1};" : "=l"(r) : "r"(__float_as_uint(v)));
    return r;
}
__device__ __forceinline__ float2 unpk(u64 p) {
    float2 r;
    r.x = __uint_as_float((unsigned int)p);
    r.y = __uint_as_float((unsigned int)(p >> 32));
    return r;
}

// smem map (bytes):
//  xs   [0, 98816)        32 x 772 floats (full x rows, once-from-DRAM)
//  t2s  [98816, +13824)   3 x 576 u64 t-round buffers; redq (1152 u64) overlays
//  w2s  [112640, +3072)   [32 tokens][12 u64] dup'd exp weights
#define OFF_T2S   98816
#define OFF_W2S   112640
#define FUSED_SMEM 115712

// ---------------- K0a (R12): q = (x[b,0,:] @ Wq) * 0.125 — grid (12,B) ----------------
__global__ void k_q_kern(const float* __restrict__ x, const float* __restrict__ Wq) {
    int b = blockIdx.y, jj = blockIdx.x, tid = threadIdx.x;
    __shared__ float xs[C];
    __shared__ float red[256];
    const float* xr = x + (size_t)b * NTOK * C;
    for (int i = tid; i < C; i += 256) xs[i] = xr[i];
    __syncthreads();
    int col = jj * 64 + (tid & 63), q = tid >> 6;
    float acc = 0.f;
    const float* wcol = Wq + (size_t)(q * 192) * C + col;
    #pragma unroll 8
    for (int c = 0; c < 192; c++)
        acc = fmaf(xs[q * 192 + c], wcol[(size_t)c * C], acc);
    red[tid] = acc;
    __syncthreads();
    if (tid < 64)
        g_q[b * C + jj * 64 + tid] =
            (red[tid] + red[tid + 64] + red[tid + 128] + red[tid + 192]) * 0.125f;
}

// ---------------- K0b (R12): t[b,c,h] — grid (32,B) x2 ----------------
#define TROWS 12
__global__ void k_t_kern(const float* __restrict__ Wkv, int cbase) {
    __shared__ float wk[TROWS * C];
    __shared__ float qs[C];
    int b = blockIdx.y, c0 = (blockIdx.x + cbase) * TROWS, tid = threadIdx.x;  // 144 thr
    for (int i = tid; i < C; i += 144) qs[i] = g_q[b * C + i];
    for (int i = tid; i < TROWS * C; i += 144)
        wk[i] = Wkv[(size_t)(c0 + i / C) * (2 * C) + (i % C)];
    __syncthreads();
    int cl = tid / 12, h = tid % 12;
    float a0 = 0.f, a1 = 0.f, a2 = 0.f, a3 = 0.f;
    #pragma unroll
    for (int j = 0; j < 16; j++) {
        int d4 = ((j + h) & 15) * 4;
        float4 w = *(const float4*)&wk[cl * C + h * 64 + d4];
        float4 q4 = *(const float4*)&qs[h * 64 + d4];
        a0 = fmaf(w.x, q4.x, a0); a1 = fmaf(w.y, q4.y, a1);
        a2 = fmaf(w.z, q4.z, a2); a3 = fmaf(w.w, q4.w, a3);
    }
    g_t[(size_t)b * C * H + (size_t)(c0 + cl) * H + h] = (a0 + a1) + (a2 + a3);
}

// ---------------- K1 fused: 384 threads, 2 CTAs/SM -> 6 warps/SMSP ----------------
__global__ void __launch_bounds__(384, 2) k_fused(const float* __restrict__ x) {
    extern __shared__ __align__(16) char dyn[];
    float* xs = (float*)dyn;
    u64* t2s = (u64*)(dyn + OFF_T2S);       // 3 x 576 u64
    u64* redq = (u64*)(dyn + OFF_T2S);      // overlay (1152 u64), used after t drained
    u64* w2s = (u64*)(dyn + OFF_W2S);       // 32 x 12 u64

    int b = blockIdx.y, ch = blockIdx.x, tid = threadIdx.x;
    int wid = tid >> 5, lane = tid & 31;
    int np = tid & 15, pp = tid >> 4;       // phase 1: token-pair lane, 24-way c part
    int g = tid >> 7, ct = tid & 127;       // phase 2: head group (0..2), column slot
    const float* tb = g_t + (size_t)b * C * H;
    const u64* tsrc = (const u64*)tb;

    unsigned sxs = (unsigned)__cvta_generic_to_shared(xs);
    unsigned st2 = (unsigned)__cvta_generic_to_shared(t2s);

    u64 ya[4][3];
    #pragma unroll
    for (int hh = 0; hh < 4; hh++) {
        #pragma unroll
        for (int pc = 0; pc < 3; pc++) ya[hh][pc] = 0ull;
    }
    float lacc = 0.f;

    #define STAGE_T(rr)                                                            \
        {                                                                          \
            unsigned _d = st2 + (unsigned)(((rr) % 3) * 4608) + tid * 8;           \
            const u64* _s = tsrc + (size_t)(rr) * 576;                             \
            asm volatile("cp.async.ca.shared.global [%0], [%1], 8;\n" ::           \
                         "r"(_d), "l"(_s + tid) : "memory");                       \
            if (tid < 192)                                                         \
                asm volatile("cp.async.ca.shared.global [%0], [%1], 8;\n" ::       \
                             "r"(_d + 3072), "l"(_s + 384 + tid) : "memory");      \
            asm volatile("cp.async.commit_group;\n" ::: "memory");                 \
        }

    #pragma unroll 1
    for (int s = 0; s < SUBS; s++) {
        const float* xrow = x + ((size_t)b * NTOK + (size_t)(ch * 256 + s * TPC)) * C;

        // ---- stage x tile (32 x 768 -> padded rows), one group ----
        #pragma unroll
        for (int j = 0; j < 16; j++) {
            int f = (tid + j * 384) * 4;
            int n = f / 768;
            asm volatile("cp.async.cg.shared.global [%0], [%1], 16;\n" ::
                         "r"(sxs + (unsigned)(f * 4 + n * 16)), "l"(xrow + f) : "memory");
        }
        asm volatile("cp.async.commit_group;\n" ::: "memory");

        STAGE_T(0);
        STAGE_T(1);

        // ---- phase 1: scores, 8 rounds of 96 c, triple-buffered t ----
        u64 acc0[6], acc1[6];
        #pragma unroll
        for (int i = 0; i < 6; i++) { acc0[i] = 0ull; acc1[i] = 0ull; }

        #pragma unroll
        for (int r = 0; r < 8; r++) {
            if (r == 7) { asm volatile("cp.async.wait_group 0;\n" ::: "memory"); }
            else        { asm volatile("cp.async.wait_group 1;\n" ::: "memory"); }
            __syncthreads();
            if (r < 6) STAGE_T(r + 2);

            const u64* tbuf = t2s + (r % 3) * 576;
            int cb = r * 96 + pp * 4;
            float xa0[4], xa1[4];
            *(float4*)xa0 = *(const float4*)&xs[np * XSTR + cb];
            *(float4*)xa1 = *(const float4*)&xs[(np + 16) * XSTR + cb];
            #pragma unroll
            for (int e = 0; e < 4; e++) {
                const u64* tp = &tbuf[(pp * 4 + e) * 6];
                ulonglong2 ta = *(const ulonglong2*)&tp[0];
                ulonglong2 tb2 = *(const ulonglong2*)&tp[2];
                ulonglong2 tc = *(const ulonglong2*)&tp[4];
                u64 d0 = dup2(xa0[e]), d1 = dup2(xa1[e]);
                FMA2(acc0[0], d0, ta.x);  FMA2(acc0[1], d0, ta.y);
                FMA2(acc0[2], d0, tb2.x); FMA2(acc0[3], d0, tb2.y);
                FMA2(acc0[4], d0, tc.x);  FMA2(acc0[5], d0, tc.y);
                FMA2(acc1[0], d1, ta.x);  FMA2(acc1[1], d1, ta.y);
                FMA2(acc1[2], d1, tb2.x); FMA2(acc1[3], d1, tb2.y);
                FMA2(acc1[4], d1, tc.x);  FMA2(acc1[5], d1, tc.y);
            }
        }
        __syncthreads();   // t2s drained and read; redq overlay now safe

        // ---- pass A: tokens 0..15 (acc0) ----
        #pragma unroll
        for (int i = 0; i < 6; i++) {
            u64 o = __shfl_xor_sync(0xffffffffu, acc0[i], 16);
            ADD2(acc0[i], o);
        }
        if (lane < 16) {
            u64* dst = &redq[(size_t)(np * 12 + wid) * 6];
            *(ulonglong2*)&dst[0] = make_ulonglong2(acc0[0], acc0[1]);
            *(ulonglong2*)&dst[2] = make_ulonglong2(acc0[2], acc0[3]);
            *(ulonglong2*)&dst[4] = make_ulonglong2(acc0[4], acc0[5]);
        }
        __syncthreads();
        if (tid < 96) {
            int tn = tid / 6, i = tid % 6;
            u64 sv = 0ull;
            #pragma unroll
            for (int p = 0; p < 12; p++) ADD2(sv, redq[(size_t)(tn * 12 + p) * 6 + i]);
            float2 a = unpk(sv);
            float e0 = __expf(a.x), e1 = __expf(a.y);
            *(ulonglong2*)&w2s[tn * 12 + 2 * i] = make_ulonglong2(dup2(e0), dup2(e1));
        }
        __syncthreads();

        // ---- pass B: tokens 16..31 (acc1) ----
        #pragma unroll
        for (int i = 0; i < 6; i++) {
            u64 o = __shfl_xor_sync(0xffffffffu, acc1[i], 16);
            ADD2(acc1[i], o);
        }
        if (lane < 16) {
            u64* dst = &redq[(size_t)(np * 12 + wid) * 6];
            *(ulonglong2*)&dst[0] = make_ulonglong2(acc1[0], acc1[1]);
            *(ulonglong2*)&dst[2] = make_ulonglong2(acc1[2], acc1[3]);
            *(ulonglong2*)&dst[4] = make_ulonglong2(acc1[4], acc1[5]);
        }
        __syncthreads();
        if (tid < 96) {
            int tn = tid / 6, i = tid % 6;
            u64 sv = 0ull;
            #pragma unroll
            for (int p = 0; p < 12; p++) ADD2(sv, redq[(size_t)(tn * 12 + p) * 6 + i]);
            float2 a = unpk(sv);
            float e0 = __expf(a.x), e1 = __expf(a.y);
            *(ulonglong2*)&w2s[(tn + 16) * 12 + 2 * i] = make_ulonglong2(dup2(e0), dup2(e1));
        }
        __syncthreads();   // w2s complete

        // ---- per-head expsum from w2s (12 collector threads) ----
        if (tid < 96) {
            int h = tid >> 3, seg = tid & 7;
            float sv = 0.f;
            #pragma unroll
            for (int k = 0; k < 4; k++)
                sv += __uint_as_float((unsigned int)w2s[(seg * 4 + k) * 12 + h]);
            sv += __shfl_xor_sync(0xffffffffu, sv, 1);
            sv += __shfl_xor_sync(0xffffffffu, sv, 2);
            sv += __shfl_xor_sync(0xffffffffu, sv, 4);
            if (!seg) lacc += sv;
        }

        // ---- phase 2: y accumulation, 100% smem; 4 heads per thread group ----
        const u64* wbase = w2s + g * 4;
        #pragma unroll 8
        for (int n = 0; n < TPC; n++) {
            ulonglong2 A = *(const ulonglong2*)&xs[n * XSTR + 4 * ct];
            u64 Bv = *(const u64*)&xs[n * XSTR + 512 + 2 * ct];
            const u64* wr = wbase + n * 12;
            ulonglong2 w01 = *(const ulonglong2*)&wr[0];
            ulonglong2 w23 = *(const ulonglong2*)&wr[2];
            FMA2(ya[0][0], A.x, w01.x); FMA2(ya[0][1], A.y, w01.x); FMA2(ya[0][2], Bv, w01.x);
            FMA2(ya[1][0], A.x, w01.y); FMA2(ya[1][1], A.y, w01.y); FMA2(ya[1][2], Bv, w01.y);
            FMA2(ya[2][0], A.x, w23.x); FMA2(ya[2][1], A.y, w23.x); FMA2(ya[2][2], Bv, w23.x);
            FMA2(ya[3][0], A.x, w23.y); FMA2(ya[3][1], A.y, w23.y); FMA2(ya[3][2], Bv, w23.y);
        }
        __syncthreads();   // xs/w2s reused next sub-chunk
    }
    #undef STAGE_T

    // ---- write y partials (unnormalized) ----
    u64* ypu = (u64*)(g_yp + (((size_t)ch * B + b) * H + g * 4) * C);
    #pragma unroll
    for (int hh = 0; hh < 4; hh++) {
        *(ulonglong2*)(ypu + (size_t)hh * 384 + 2 * ct) = make_ulonglong2(ya[hh][0], ya[hh][1]);
        ypu[(size_t)hh * 384 + 256 + ct] = ya[hh][2];
    }

    // ---- write chunk expsums ----
    if (tid < 96 && (tid & 7) == 0)
        g_cl[((size_t)b * CH + ch) * H + (tid >> 3)] = lacc;
}

// ---------------- K2 (R12): cls — one head per CTA, grid (12, B) ----------------
__global__ void k_cls(const float* __restrict__ Wkv) {
    int h = blockIdx.x, b = blockIdx.y, tid = threadIdx.x;
    __shared__ float y_s[C];
    __shared__ float red[256];
    __shared__ float rsc;

    if (tid == 0) {
        float L = 0.f;
        #pragma unroll
        for (int ch = 0; ch < CH; ch++) L += g_cl[((size_t)b * CH + ch) * H + h];
        rsc = 1.f / L;
    }
    __syncthreads();

    float r = rsc;
    for (int i = tid; i < C; i += 256) {
        float s = 0.f;
        #pragma unroll
        for (int ch = 0; ch < CH; ch++)
            s += g_yp[(((size_t)ch * B + b) * H + h) * C + i];
        y_s[i] = s * r;
    }
    __syncthreads();

    int col = h * 64 + (tid & 63), q = tid >> 6;
    float acc = 0.f;
    const float* wcol = Wkv + (size_t)(q * 192) * (2 * C) + C + col;
    #pragma unroll 8
    for (int c = 0; c < 192; c++)
        acc = fmaf(y_s[q * 192 + c], wcol[(size_t)c * (2 * C)], acc);
    red[tid] = acc;
    __syncthreads();
    if (tid < 64)
        g_cls[b * C + h * 64 + tid] =
            red[tid] + red[tid + 64] + red[tid + 128] + red[tid + 192];
}

// ---------------- K3 (R12): out = cls @ Wp + bp — grid (12, B) ----------------
__global__ void k_out(const float* __restrict__ Wp, const float* __restrict__ bp,
                      float* __restrict__ out) {
    int b = blockIdx.y, jj = blockIdx.x, tid = threadIdx.x;
    __shared__ float c_s[C];
    __shared__ float red[256];
    for (int i = tid; i < C; i += 256) c_s[i] = g_cls[b * C + i];
    __syncthreads();
    int col = jj * 64 + (tid & 63), q = tid >> 6;
    float acc = 0.f;
    const float* wcol = Wp + (size_t)(q * 192) * C + col;
    #pragma unroll 8
    for (int c = 0; c < 192; c++)
        acc = fmaf(c_s[q * 192 + c], wcol[(size_t)c * C], acc);
    red[tid] = acc;
    __syncthreads();
    if (tid < 64) {
        int j = jj * 64 + tid;
        out[b * C + j] = red[tid] + red[tid + 64] + red[tid + 128] + red[tid + 192] + bp[j];
    }
}

// ---------------- launcher ----------------
extern "C" void kernel_launch(void* const* d_in, const int* in_sizes, int n_in,
                              void* d_out, int out_size) {
    const float* x   = (const float*)d_in[0];
    const float* Wq  = (const float*)d_in[1];
    const float* Wkv = (const float*)d_in[2];
    const float* Wp  = (const float*)d_in[3];
    const float* bp  = (const float*)d_in[4];
    float* out = (float*)d_out;

    cudaFuncSetAttribute(k_fused, cudaFuncAttributeMaxDynamicSharedMemorySize, FUSED_SMEM);

    k_q_kern<<<dim3(12, B), 256>>>(x, Wq);             // launch #1
    k_t_kern<<<dim3(32, B), 144>>>(Wkv, 0);            // launch #2
    k_t_kern<<<dim3(32, B), 144>>>(Wkv, 32);           // launch #3
    k_fused <<<dim3(CH, B), 384, FUSED_SMEM>>>(x);     // launch #4 -> profiled
    k_cls   <<<dim3(12, B), 256>>>(Wkv);               // launch #5
    k_out   <<<dim3(12, B), 256>>>(Wp, bp, out);       // launch #6
}

// round 15
// speedup vs baseline: 1.6625x; 1.1359x over previous
#include <cuda_runtime.h>
#include <math.h>

#define B 32
#define NTOK 4096
#define C 768
#define H 12
#define CH 16           // outer chunks per batch (256 tokens each)
#define SUBS 8          // sub-chunks per CTA
#define TPC 32          // tokens per sub-chunk tile
#define XSTR 772        // xs row stride in floats (768 + 4 pad)

typedef unsigned long long u64;

// ---------------- scratch ----------------
__device__ __align__(16) float g_q[B * C];
__device__ __align__(16) float g_t[B * C * H];
__device__ __align__(16) float g_cl[B * CH * H];
__device__ __align__(16) float g_yp[CH * B * H * C];
__device__ __align__(16) float g_cls[B * C];

// ---------------- f32x2 helpers ----------------
#define FMA2(d, a, b) asm("fma.rn.f32x2 %0, %1, %2, %0;" : "+l"(d) : "l"(a), "l"(b))
#define ADD2(d, a)    asm("add.rn.f32x2 %0, %0, %1;"     : "+l"(d) : "l"(a))

__device__ __forceinline__ u64 dup2(float v) {
    u64 r;
    asm("mov.b64 %0, {%1, %1};" : "=l"(r) : "r"(__float_as_uint(v)));
    return r;
}
__device__ __forceinline__ float2 unpk(u64 p) {
    float2 r;
    r.x = __uint_as_float((unsigned int)p);
    r.y = __uint_as_float((unsigned int)(p >> 32));
    return r;
}

// smem map (bytes) — identical to R12:
//  xs   [0, 98816)        32 x 772 floats
//  t2s  [98816, +12288)   2 x 768 u64 t buffers; redq overlays
//  w2s  [111104, +3072)   [32][12] u64 dup'd exp weights
//  redl [114176, +128)
#define OFF_T2S   98816
#define OFF_W2S   111104
#define OFF_REDL  114176
#define FUSED_SMEM 114304

// ---------------- K0a (R12): q = (x[b,0,:] @ Wq) * 0.125 — grid (12,B) ----------------
__global__ void k_q_kern(const float* __restrict__ x, const float* __restrict__ Wq) {
    int b = blockIdx.y, jj = blockIdx.x, tid = threadIdx.x;
    __shared__ float xs[C];
    __shared__ float red[256];
    const float* xr = x + (size_t)b * NTOK * C;
    for (int i = tid; i < C; i += 256) xs[i] = xr[i];
    __syncthreads();
    int col = jj * 64 + (tid & 63), q = tid >> 6;
    float acc = 0.f;
    const float* wcol = Wq + (size_t)(q * 192) * C + col;
    #pragma unroll 8
    for (int c = 0; c < 192; c++)
        acc = fmaf(xs[q * 192 + c], wcol[(size_t)c * C], acc);
    red[tid] = acc;
    __syncthreads();
    if (tid < 64)
        g_q[b * C + jj * 64 + tid] =
            (red[tid] + red[tid + 64] + red[tid + 128] + red[tid + 192]) * 0.125f;
}

// ---------------- K0b (R12): t[b,c,h] — grid (32,B) x2 ----------------
#define TROWS 12
__global__ void k_t_kern(const float* __restrict__ Wkv, int cbase) {
    __shared__ float wk[TROWS * C];
    __shared__ float qs[C];
    int b = blockIdx.y, c0 = (blockIdx.x + cbase) * TROWS, tid = threadIdx.x;  // 144 thr
    for (int i = tid; i < C; i += 144) qs[i] = g_q[b * C + i];
    for (int i = tid; i < TROWS * C; i += 144)
        wk[i] = Wkv[(size_t)(c0 + i / C) * (2 * C) + (i % C)];
    __syncthreads();
    int cl = tid / 12, h = tid % 12;
    float a0 = 0.f, a1 = 0.f, a2 = 0.f, a3 = 0.f;
    #pragma unroll
    for (int j = 0; j < 16; j++) {
        int d4 = ((j + h) & 15) * 4;
        float4 w = *(const float4*)&wk[cl * C + h * 64 + d4];
        float4 q4 = *(const float4*)&qs[h * 64 + d4];
        a0 = fmaf(w.x, q4.x, a0); a1 = fmaf(w.y, q4.y, a1);
        a2 = fmaf(w.z, q4.z, a2); a3 = fmaf(w.w, q4.w, a3);
    }
    g_t[(size_t)b * C * H + (size_t)(c0 + cl) * H + h] = (a0 + a1) + (a2 + a3);
}

// ---------------- K1 fused: R12 + cross-subchunk x prefetch behind phase 2 ----------------
// grid (CH, B) = (16, 32), 256 threads, 2 CTAs/SM.
__global__ void __launch_bounds__(256, 2) k_fused(const float* __restrict__ x) {
    extern __shared__ __align__(16) char dyn[];
    float* xs = (float*)dyn;
    u64* t2s = (u64*)(dyn + OFF_T2S);
    u64* w2s = (u64*)(dyn + OFF_W2S);
    float* redl = (float*)(dyn + OFF_REDL);

    int b = blockIdx.y, ch = blockIdx.x, tid = threadIdx.x;
    int wid = tid >> 5, lane = tid & 31;
    int pp = tid >> 4, np = tid & 15;
    int g = tid >> 7, ct = tid & 127;
    const float* tb = g_t + (size_t)b * C * H;
    const u64* tsrc = (const u64*)tb;
    const float* xbase = x + ((size_t)b * NTOK + (size_t)ch * 256) * C;

    unsigned sxs = (unsigned)__cvta_generic_to_shared(xs);
    unsigned st2 = (unsigned)__cvta_generic_to_shared(t2s);

    #define STAGE_T0()                                                          \
        {                                                                       \
            unsigned d0 = st2 + tid * 8;                                        \
            asm volatile("cp.async.ca.shared.global [%0], [%1], 8;\n" ::        \
                         "r"(d0), "l"(tsrc + tid) : "memory");                  \
            asm volatile("cp.async.ca.shared.global [%0], [%1], 8;\n" ::        \
                         "r"(d0 + 2048), "l"(tsrc + 256 + tid) : "memory");     \
            asm volatile("cp.async.ca.shared.global [%0], [%1], 8;\n" ::        \
                         "r"(d0 + 4096), "l"(tsrc + 512 + tid) : "memory");     \
            asm volatile("cp.async.commit_group;\n" ::: "memory");              \
        }

    u64 ya[6][3];
    #pragma unroll
    for (int hh = 0; hh < 6; hh++) {
        #pragma unroll
        for (int pc = 0; pc < 3; pc++) ya[hh][pc] = 0ull;
    }
    float lacc[4] = {0.f, 0.f, 0.f, 0.f};

    // ---- initial staging: full x tile (sub-chunk 0) + t round 0 ----
    #pragma unroll
    for (int j = 0; j < 24; j++) {
        int f = tid * 4 + j * 1024;
        int n = f / 768;
        asm volatile("cp.async.cg.shared.global [%0], [%1], 16;\n" ::
                     "r"(sxs + (unsigned)(f * 4 + n * 16)), "l"(xbase + f) : "memory");
    }
    asm volatile("cp.async.commit_group;\n" ::: "memory");
    STAGE_T0();

    #pragma unroll 1
    for (int s = 0; s < SUBS; s++) {
        // ---- phase 1: scores, 6 rounds of 128 c, double-buffered t ----
        u64 acc0[6], acc1[6];
        #pragma unroll
        for (int i = 0; i < 6; i++) { acc0[i] = 0ull; acc1[i] = 0ull; }

        #pragma unroll
        for (int r = 0; r < 6; r++) {
            asm volatile("cp.async.wait_group 0;\n" ::: "memory");
            __syncthreads();
            if (r < 5) {
                unsigned d = st2 + (unsigned)(((r + 1) & 1) * 6144) + tid * 8;
                const u64* srcr = tsrc + (r + 1) * 768;
                asm volatile("cp.async.ca.shared.global [%0], [%1], 8;\n" ::
                             "r"(d), "l"(srcr + tid) : "memory");
                asm volatile("cp.async.ca.shared.global [%0], [%1], 8;\n" ::
                             "r"(d + 2048), "l"(srcr + 256 + tid) : "memory");
                asm volatile("cp.async.ca.shared.global [%0], [%1], 8;\n" ::
                             "r"(d + 4096), "l"(srcr + 512 + tid) : "memory");
                asm volatile("cp.async.commit_group;\n" ::: "memory");
            }

            const u64* tbuf = t2s + (r & 1) * 768;
            int cb = r * 128 + pp * 8;
            float xa0[8], xa1[8];
            *(float4*)&xa0[0] = *(const float4*)&xs[np * XSTR + cb];
            *(float4*)&xa0[4] = *(const float4*)&xs[np * XSTR + cb + 4];
            *(float4*)&xa1[0] = *(const float4*)&xs[(np + 16) * XSTR + cb];
            *(float4*)&xa1[4] = *(const float4*)&xs[(np + 16) * XSTR + cb + 4];
            #pragma unroll
            for (int e = 0; e < 8; e++) {
                const u64* tp = &tbuf[(pp * 8 + e) * 6];
                ulonglong2 ta = *(const ulonglong2*)&tp[0];
                ulonglong2 tb2 = *(const ulonglong2*)&tp[2];
                ulonglong2 tc = *(const ulonglong2*)&tp[4];
                u64 d0 = dup2(xa0[e]);
                u64 d1 = dup2(xa1[e]);
                FMA2(acc0[0], d0, ta.x);  FMA2(acc0[1], d0, ta.y);
                FMA2(acc0[2], d0, tb2.x); FMA2(acc0[3], d0, tb2.y);
                FMA2(acc0[4], d0, tc.x);  FMA2(acc0[5], d0, tc.y);
                FMA2(acc1[0], d1, ta.x);  FMA2(acc1[1], d1, ta.y);
                FMA2(acc1[2], d1, tb2.x); FMA2(acc1[3], d1, tb2.y);
                FMA2(acc1[4], d1, tc.x);  FMA2(acc1[5], d1, tc.y);
            }
        }
        __syncthreads();   // t2s drained; redq overlay safe

        // ---- K-split reduction + exp (no max) ----
        ulonglong2* redq = (ulonglong2*)t2s;
        redq[tid]       = make_ulonglong2(acc0[0], acc0[1]);
        redq[256 + tid] = make_ulonglong2(acc0[2], acc0[3]);
        redq[512 + tid] = make_ulonglong2(acc0[4], acc0[5]);
        __syncthreads();
        u64 sx = 0ull, sy = 0ull;
        if (wid < 3 && lane < 16) {
            #pragma unroll
            for (int p2 = 0; p2 < 16; p2++) {
                ulonglong2 v = redq[wid * 256 + p2 * 16 + lane];
                ADD2(sx, v.x); ADD2(sy, v.y);
            }
        }
        __syncthreads();
        redq[tid]       = make_ulonglong2(acc1[0], acc1[1]);
        redq[256 + tid] = make_ulonglong2(acc1[2], acc1[3]);
        redq[512 + tid] = make_ulonglong2(acc1[4], acc1[5]);
        __syncthreads();
        if (wid < 3 && lane < 16) {
            float2 a0 = unpk(sx), a1 = unpk(sy);
            float e0 = __expf(a0.x), e1 = __expf(a0.y);
            float e2 = __expf(a1.x), e3 = __expf(a1.y);
            int base = lane * 12 + 4 * wid;
            *(ulonglong2*)&w2s[base]     = make_ulonglong2(dup2(e0), dup2(e1));
            *(ulonglong2*)&w2s[base + 2] = make_ulonglong2(dup2(e2), dup2(e3));
            lacc[0] += e0; lacc[1] += e1; lacc[2] += e2; lacc[3] += e3;
        } else if (wid < 6 && lane < 16) {
            int j2 = wid - 3;
            u64 tx = 0ull, ty = 0ull;
            #pragma unroll
            for (int p2 = 0; p2 < 16; p2++) {
                ulonglong2 v = redq[j2 * 256 + p2 * 16 + lane];
                ADD2(tx, v.x); ADD2(ty, v.y);
            }
            float2 a0 = unpk(tx), a1 = unpk(ty);
            float e0 = __expf(a0.x), e1 = __expf(a0.y);
            float e2 = __expf(a1.x), e3 = __expf(a1.y);
            int base = (lane + 16) * 12 + 4 * j2;
            *(ulonglong2*)&w2s[base]     = make_ulonglong2(dup2(e0), dup2(e1));
            *(ulonglong2*)&w2s[base + 2] = make_ulonglong2(dup2(e2), dup2(e3));
            lacc[0] += e0; lacc[1] += e1; lacc[2] += e2; lacc[3] += e3;
        }
        __syncthreads();   // w2s ready

        // ---- phase 2: y accumulation, smem-only; 4 token-groups with
        //      cross-subchunk x prefetch into just-freed rows ----
        const u64* wbase = w2s + g * 6;
        const float* xnext = xbase + (size_t)((s + 1) * TPC) * C;
        int stage_next = (s < SUBS - 1);

        #pragma unroll
        for (int grp = 0; grp < 4; grp++) {
            #pragma unroll
            for (int nn = 0; nn < 8; nn++) {
                int n = grp * 8 + nn;
                ulonglong2 A = *(const ulonglong2*)&xs[n * XSTR + 4 * ct];
                u64 Bv = *(const u64*)&xs[n * XSTR + 512 + 2 * ct];
                const u64* wr = wbase + n * 12;
                ulonglong2 w01 = *(const ulonglong2*)&wr[0];
                ulonglong2 w23 = *(const ulonglong2*)&wr[2];
                ulonglong2 w45 = *(const ulonglong2*)&wr[4];
                FMA2(ya[0][0], A.x, w01.x); FMA2(ya[0][1], A.y, w01.x); FMA2(ya[0][2], Bv, w01.x);
                FMA2(ya[1][0], A.x, w01.y); FMA2(ya[1][1], A.y, w01.y); FMA2(ya[1][2], Bv, w01.y);
                FMA2(ya[2][0], A.x, w23.x); FMA2(ya[2][1], A.y, w23.x); FMA2(ya[2][2], Bv, w23.x);
                FMA2(ya[3][0], A.x, w23.y); FMA2(ya[3][1], A.y, w23.y); FMA2(ya[3][2], Bv, w23.y);
                FMA2(ya[4][0], A.x, w45.x); FMA2(ya[4][1], A.y, w45.x); FMA2(ya[4][2], Bv, w45.x);
                FMA2(ya[5][0], A.x, w45.y); FMA2(ya[5][1], A.y, w45.y); FMA2(ya[5][2], Bv, w45.y);
            }
            if (stage_next) {
                __syncthreads();   // group grp rows fully consumed by all warps
                #pragma unroll
                for (int j = 0; j < 6; j++) {
                    int f = grp * 6144 + tid * 4 + j * 1024;
                    int n2 = f / 768;
                    asm volatile("cp.async.cg.shared.global [%0], [%1], 16;\n" ::
                                 "r"(sxs + (unsigned)(f * 4 + n2 * 16)), "l"(xnext + f) : "memory");
                }
                asm volatile("cp.async.commit_group;\n" ::: "memory");
            }
        }
        if (stage_next) STAGE_T0();   // t round 0 for next sub-chunk
    }
    #undef STAGE_T0

    // ---- write y partials (unnormalized) ----
    u64* ypu = (u64*)(g_yp + (((size_t)ch * B + b) * H + g * 6) * C);
    #pragma unroll
    for (int hh = 0; hh < 6; hh++) {
        *(ulonglong2*)(ypu + (size_t)hh * 384 + 2 * ct) = make_ulonglong2(ya[hh][0], ya[hh][1]);
        ypu[(size_t)hh * 384 + 256 + ct] = ya[hh][2];
    }

    // ---- chunk expsums ----
    #pragma unroll
    for (int i = 0; i < 4; i++) {
        #pragma unroll
        for (int o = 16; o; o >>= 1)
            lacc[i] += __shfl_xor_sync(0xffffffffu, lacc[i], o);
    }
    if (wid >= 3 && wid < 6 && lane == 0) {
        #pragma unroll
        for (int i = 0; i < 4; i++) redl[(wid - 3) * 4 + i] = lacc[i];
    }
    __syncthreads();
    if (wid < 3 && lane == 0) {
        #pragma unroll
        for (int i = 0; i < 4; i++)
            g_cl[((size_t)b * CH + ch) * H + 4 * wid + i] = lacc[i] + redl[wid * 4 + i];
    }
}

// ---------------- K2 (R12): cls — one head per CTA, grid (12, B) ----------------
__global__ void k_cls(const float* __restrict__ Wkv) {
    int h = blockIdx.x, b = blockIdx.y, tid = threadIdx.x;
    __shared__ float y_s[C];
    __shared__ float red[256];
    __shared__ float rsc;

    if (tid == 0) {
        float L = 0.f;
        #pragma unroll
        for (int ch = 0; ch < CH; ch++) L += g_cl[((size_t)b * CH + ch) * H + h];
        rsc = 1.f / L;
    }
    __syncthreads();

    float r = rsc;
    for (int i = tid; i < C; i += 256) {
        float s = 0.f;
        #pragma unroll
        for (int ch = 0; ch < CH; ch++)
            s += g_yp[(((size_t)ch * B + b) * H + h) * C + i];
        y_s[i] = s * r;
    }
    __syncthreads();

    int col = h * 64 + (tid & 63), q = tid >> 6;
    float acc = 0.f;
    const float* wcol = Wkv + (size_t)(q * 192) * (2 * C) + C + col;
    #pragma unroll 8
    for (int c = 0; c < 192; c++)
        acc = fmaf(y_s[q * 192 + c], wcol[(size_t)c * (2 * C)], acc);
    red[tid] = acc;
    __syncthreads();
    if (tid < 64)
        g_cls[b * C + h * 64 + tid] =
            red[tid] + red[tid + 64] + red[tid + 128] + red[tid + 192];
}

// ---------------- K3 (R12): out = cls @ Wp + bp — grid (12, B) ----------------
__global__ void k_out(const float* __restrict__ Wp, const float* __restrict__ bp,
                      float* __restrict__ out) {
    int b = blockIdx.y, jj = blockIdx.x, tid = threadIdx.x;
    __shared__ float c_s[C];
    __shared__ float red[256];
    for (int i = tid; i < C; i += 256) c_s[i] = g_cls[b * C + i];
    __syncthreads();
    int col = jj * 64 + (tid & 63), q = tid >> 6;
    float acc = 0.f;
    const float* wcol = Wp + (size_t)(q * 192) * C + col;
    #pragma unroll 8
    for (int c = 0; c < 192; c++)
        acc = fmaf(c_s[q * 192 + c], wcol[(size_t)c * C], acc);
    red[tid] = acc;
    __syncthreads();
    if (tid < 64) {
        int j = jj * 64 + tid;
        out[b * C + j] = red[tid] + red[tid + 64] + red[tid + 128] + red[tid + 192] + bp[j];
    }
}

// ---------------- launcher ----------------
extern "C" void kernel_launch(void* const* d_in, const int* in_sizes, int n_in,
                              void* d_out, int out_size) {
    const float* x   = (const float*)d_in[0];
    const float* Wq  = (const float*)d_in[1];
    const float* Wkv = (const float*)d_in[2];
    const float* Wp  = (const float*)d_in[3];
    const float* bp  = (const float*)d_in[4];
    float* out = (float*)d_out;

    cudaFuncSetAttribute(k_fused, cudaFuncAttributeMaxDynamicSharedMemorySize, FUSED_SMEM);

    k_q_kern<<<dim3(12, B), 256>>>(x, Wq);             // launch #1
    k_t_kern<<<dim3(32, B), 144>>>(Wkv, 0);            // launch #2
    k_t_kern<<<dim3(32, B), 144>>>(Wkv, 32);           // launch #3
    k_fused <<<dim3(CH, B), 256, FUSED_SMEM>>>(x);     // launch #4 -> profiled
    k_cls   <<<dim3(12, B), 256>>>(Wkv);               // launch #5
    k_out   <<<dim3(12, B), 256>>>(Wp, bp, out);       // launch #6
}